// round 15
// baseline (speedup 1.0000x reference)
#include <cuda_runtime.h>
#include <math.h>

#define V 50257
#define H 1024
#define T 10
#define LROWS 32
#define NLB ((V + LROWS - 1) / LROWS)   // 1571 logits blocks (512 threads each)

// ---------------- device scratch (no allocations allowed) ----------------
__device__ __align__(16) float g_h[2][H];
__device__ __align__(16) float g_c[2][H];
__device__ __align__(16) float g_enc[T * H];
__device__ __align__(16) float g_prev[H];
__device__ __align__(16) float g_q[H];
__device__ __align__(16) float g_ctx[H];
__device__ __align__(16) float g_gate[4 * H];    // decoder partial gate sums
__device__ __align__(16) float g_xproj[T * 4 * H]; // enc W_ih@x_t + biases
__device__ int   g_tok[T];
__device__ float g_pval[NLB + 32];
__device__ int   g_pidx[NLB + 32];
__device__ unsigned int g_cnt1;
__device__ unsigned int g_cnt2;
__device__ unsigned int g_prev_ready;   // argmax-completion counter (per step)

__device__ __forceinline__ float sigm(float x) { return 1.f / (1.f + expf(-x)); }
__device__ __forceinline__ float dot4(float4 a, float4 b) {
    return a.x * b.x + a.y * b.y + a.z * b.z + a.w * b.w;
}

// ---------------- init: tokens, states, poison-safe tail zero -------------
__global__ void k_init(const void* __restrict__ seq_raw,
                       float* __restrict__ out, int out_size) {
    int tid = blockIdx.x * blockDim.x + threadIdx.x;
    if (tid == 0) {
        const long long* s64 = (const long long*)seq_raw;
        bool ok64 = true;
        for (int i = 0; i < T; i++) {
            long long v = s64[i];
            if (v < 0 || v >= V) { ok64 = false; break; }
        }
        const int* s32 = (const int*)seq_raw;
        for (int i = 0; i < T; i++) g_tok[i] = ok64 ? (int)s64[i] : s32[i];
        g_cnt1 = 0; g_cnt2 = 0; g_prev_ready = 0;
    }
    int stride = gridDim.x * blockDim.x;
    for (int i = tid; i < H; i += stride) {
        g_h[0][i] = 0.f; g_c[0][i] = 0.f; g_prev[i] = 0.f;
    }
    // logits region [0, T*V) is fully overwritten each step; zero only the tail
    for (int i = T * V + tid; i < out_size; i += stride) out[i] = 0.f;
}

// ------- hoisted input projection: xproj[t] = W_ih x_t + b_ih + b_hh ------
__global__ void k_xproj(const float* __restrict__ w_ih,
                        const float* __restrict__ b_ih,
                        const float* __restrict__ b_hh,
                        const float* __restrict__ embeds) {
    int tid  = threadIdx.x;
    int warp = tid >> 5;
    int lane = tid & 31;
    int j    = blockIdx.x * 2 + (warp >> 2);
    int gate = warp & 3;

    const float4* wi = (const float4*)w_ih + (size_t)(gate * H + j) * 256;
    float4 w[8];
#pragma unroll
    for (int i = 0; i < 8; i++) w[i] = wi[lane + 32 * i];

    float acc[T];
#pragma unroll
    for (int t = 0; t < T; t++) {
        const float4* x4 = (const float4*)(embeds + (size_t)g_tok[t] * H);
        float a = 0.f;
#pragma unroll
        for (int i = 0; i < 8; i++) a += dot4(w[i], x4[lane + 32 * i]);
        acc[t] = a;
    }
#pragma unroll
    for (int t = 0; t < T; t++)
        for (int off = 16; off > 0; off >>= 1)
            acc[t] += __shfl_down_sync(0xffffffffu, acc[t], off);
    if (lane == 0) {
        int row = gate * H + j;
        float b = b_ih[row] + b_hh[row];
#pragma unroll
        for (int t = 0; t < T; t++)
            g_xproj[t * 4 * H + row] = acc[t] + b;
    }
}

// ------- encoder LSTM step: hidden part only (W_hh@h), 16MB/step ---------
__global__ void k_lstm_enc(const float* __restrict__ w_hh,
                           int step, int bi) {
    int tid  = threadIdx.x;
    int warp = tid >> 5;
    int lane = tid & 31;
    int j    = blockIdx.x * 2 + (warp >> 2);
    int gate = warp & 3;

    const float4* h4 = (const float4*)g_h[bi];
    const float4* wh = (const float4*)w_hh + (size_t)(gate * H + j) * 256;

    float acc = 0.f;
#pragma unroll
    for (int i = 0; i < 8; i++) {
        int k = lane + 32 * i;
        acc += dot4(wh[k], h4[k]);
    }
    for (int off = 16; off > 0; off >>= 1)
        acc += __shfl_down_sync(0xffffffffu, acc, off);

    __shared__ float s[8];
    if (lane == 0) s[warp] = acc;
    __syncthreads();
    if (tid < 2) {
        int u = blockIdx.x * 2 + tid;
        const float* xp = g_xproj + step * 4 * H;
        float gi = s[tid * 4 + 0] + xp[u];
        float gf = s[tid * 4 + 1] + xp[H + u];
        float gg = s[tid * 4 + 2] + xp[2 * H + u];
        float go = s[tid * 4 + 3] + xp[3 * H + u];
        float i_ = sigm(gi), f_ = sigm(gf), g_ = tanhf(gg), o_ = sigm(go);
        float cn = f_ * g_c[bi][u] + i_ * g_;
        float hn = o_ * tanhf(cn);
        g_c[1 - bi][u] = cn;
        g_h[1 - bi][u] = hn;
        g_enc[step * H + u] = hn;
    }
}

// ---------------- q = wa^T h, then last block does softmax+ctx -----------
__global__ void k_qattn(const float* __restrict__ wa, int bi) {
    int tid  = threadIdx.x;
    int lane = tid & 31;
    int warp = tid >> 5;
    int col  = blockIdx.x * 32 + lane;
    const float* h = g_h[bi];

    float acc = 0.f;
    for (int i = warp; i < H; i += 8) acc += h[i] * wa[(size_t)i * H + col];
    __shared__ float s[256];
    s[tid] = acc;
    __syncthreads();
    for (int off = 128; off >= 32; off >>= 1) {
        if (tid < off) s[tid] += s[tid + off];
        __syncthreads();
    }
    if (tid < 32) g_q[col] = s[tid];

    __shared__ int s_last;
    __threadfence();
    if (tid == 0) s_last = (atomicAdd(&g_cnt1, 1u) == gridDim.x - 1);
    __syncthreads();
    if (!s_last) return;
    if (tid == 0) g_cnt1 = 0;

    float at[T];
#pragma unroll
    for (int t = 0; t < T; t++) at[t] = 0.f;
    for (int k = tid; k < H; k += 256) {
        float qv = g_q[k];
#pragma unroll
        for (int t = 0; t < T; t++) at[t] += qv * g_enc[t * H + k];
    }
#pragma unroll
    for (int t = 0; t < T; t++)
        for (int off = 16; off > 0; off >>= 1)
            at[t] += __shfl_down_sync(0xffffffffu, at[t], off);
    __shared__ float s2[T * 8];
    if (lane == 0) {
#pragma unroll
        for (int t = 0; t < T; t++) s2[t * 8 + warp] = at[t];
    }
    __syncthreads();
    __shared__ float sa[T];
    if (tid == 0) {
        float sc[T];
        float m = -INFINITY;
#pragma unroll
        for (int t = 0; t < T; t++) {
            float v = 0.f;
#pragma unroll
            for (int w = 0; w < 8; w++) v += s2[t * 8 + w];
            sc[t] = v;
            m = fmaxf(m, v);
        }
        float sum = 0.f;
#pragma unroll
        for (int t = 0; t < T; t++) { float e = expf(sc[t] - m); sa[t] = e; sum += e; }
#pragma unroll
        for (int t = 0; t < T; t++) sa[t] /= sum;
    }
    __syncthreads();
    for (int k = tid; k < H; k += 256) {
        float v = 0.f;
#pragma unroll
        for (int t = 0; t < T; t++) v += sa[t] * g_enc[t * H + k];
        g_ctx[k] = v;
    }
}

// ------- decoder part 1 (prev-independent): g_gate = Wih[:,H:]ctx + Whh h -
__global__ void k_dec_pre(const float* __restrict__ w_ih,  // (4H, 2H)
                          const float* __restrict__ w_hh,  // (4H, H)
                          int bi) {
    int tid  = threadIdx.x;
    int warp = tid >> 5;
    int lane = tid & 31;
    int j    = blockIdx.x * 2 + (warp >> 2);
    int gate = warp & 3;

    const float4* h4 = (const float4*)g_h[bi];
    const float4* c4 = (const float4*)g_ctx;
    const float4* wi = (const float4*)w_ih + (size_t)(gate * H + j) * 512 + 256;
    const float4* wh = (const float4*)w_hh + (size_t)(gate * H + j) * 256;

    float acc = 0.f;
#pragma unroll
    for (int i = 0; i < 8; i++) {
        int k = lane + 32 * i;
        acc += dot4(wi[k], c4[k]);
        acc += dot4(wh[k], h4[k]);
    }
    for (int off = 16; off > 0; off >>= 1)
        acc += __shfl_down_sync(0xffffffffu, acc, off);
    if (lane == 0) g_gate[gate * H + j] = acc;
}

// ------- decoder part 2 (front end, step 0): prev term + cell update ------
__global__ void k_dec_fin(const float* __restrict__ w_ih,  // (4H, 2H)
                          const float* __restrict__ b_ih,
                          const float* __restrict__ b_hh,
                          int bi) {
    int tid  = threadIdx.x;
    int warp = tid >> 5;
    int lane = tid & 31;
    int j    = blockIdx.x * 2 + (warp >> 2);
    int gate = warp & 3;

    const float4* p4 = (const float4*)g_prev;
    const float4* wi = (const float4*)w_ih + (size_t)(gate * H + j) * 512;

    float acc = 0.f;
#pragma unroll
    for (int i = 0; i < 8; i++) {
        int k = lane + 32 * i;
        float4 v = p4[k];
        v.x = fmaxf(v.x, 0.f); v.y = fmaxf(v.y, 0.f);
        v.z = fmaxf(v.z, 0.f); v.w = fmaxf(v.w, 0.f);
        acc += dot4(wi[k], v);
    }
    for (int off = 16; off > 0; off >>= 1)
        acc += __shfl_down_sync(0xffffffffu, acc, off);

    __shared__ float s[8];
    if (lane == 0) s[warp] = acc;
    __syncthreads();
    if (tid < 2) {
        int u = blockIdx.x * 2 + tid;
        float gi = s[tid * 4 + 0] + g_gate[0 * H + u] + b_ih[u]         + b_hh[u];
        float gf = s[tid * 4 + 1] + g_gate[1 * H + u] + b_ih[H + u]     + b_hh[H + u];
        float gg = s[tid * 4 + 2] + g_gate[2 * H + u] + b_ih[2 * H + u] + b_hh[2 * H + u];
        float go = s[tid * 4 + 3] + g_gate[3 * H + u] + b_ih[3 * H + u] + b_hh[3 * H + u];
        float i_ = sigm(gi), f_ = sigm(gf), g_ = tanhf(gg), o_ = sigm(go);
        float cn = f_ * g_c[bi][u] + i_ * g_;
        float hn = o_ * tanhf(cn);
        g_c[1 - bi][u] = cn;
        g_h[1 - bi][u] = hn;
    }
}

// ------- decoder part 2 (steps 1..9): prefetch weights, spin on argmax ----
// Runs on s2 concurrent with logits(step-1); weights load overlaps the GEMV,
// then waits for g_prev_ready >= step (set by the logits argmax tail) and
// finishes the cell update in ~1-2us. g_prev read via __ldcg (L2-coherent).
__global__ void k_dec_fin_spin(const float* __restrict__ w_ih,
                               const float* __restrict__ b_ih,
                               const float* __restrict__ b_hh,
                               int bi, unsigned target) {
    int tid  = threadIdx.x;
    int warp = tid >> 5;
    int lane = tid & 31;
    int j    = blockIdx.x * 2 + (warp >> 2);
    int gate = warp & 3;

    const float4* wi = (const float4*)w_ih + (size_t)(gate * H + j) * 512;
    float4 w[8];
#pragma unroll
    for (int i = 0; i < 8; i++) w[i] = wi[lane + 32 * i];   // prefetch
    __threadfence_block();   // keep loads before the spin

    if (tid == 0) {
        while (atomicAdd(&g_prev_ready, 0u) < target) {}
    }
    __syncthreads();

    float acc = 0.f;
#pragma unroll
    for (int i = 0; i < 8; i++) {
        int k = lane + 32 * i;
        float4 v = __ldcg((const float4*)g_prev + k);
        v.x = fmaxf(v.x, 0.f); v.y = fmaxf(v.y, 0.f);
        v.z = fmaxf(v.z, 0.f); v.w = fmaxf(v.w, 0.f);
        acc += dot4(w[i], v);
    }
    for (int off = 16; off > 0; off >>= 1)
        acc += __shfl_down_sync(0xffffffffu, acc, off);

    __shared__ float s[8];
    if (lane == 0) s[warp] = acc;
    __syncthreads();
    if (tid < 2) {
        int u = blockIdx.x * 2 + tid;
        float gi = s[tid * 4 + 0] + g_gate[0 * H + u] + b_ih[u]         + b_hh[u];
        float gf = s[tid * 4 + 1] + g_gate[1 * H + u] + b_ih[H + u]     + b_hh[H + u];
        float gg = s[tid * 4 + 2] + g_gate[2 * H + u] + b_ih[2 * H + u] + b_hh[2 * H + u];
        float go = s[tid * 4 + 3] + g_gate[3 * H + u] + b_ih[3 * H + u] + b_hh[3 * H + u];
        float i_ = sigm(gi), f_ = sigm(gf), g_ = tanhf(gg), o_ = sigm(go);
        float cn = f_ * g_c[bi][u] + i_ * g_;
        float hn = o_ * tanhf(cn);
        g_c[1 - bi][u] = cn;
        g_h[1 - bi][u] = hn;
    }
}

// ---- logits: 512 threads, 16 warps x 2 rows, fused argmax + ready flag ---
__global__ void __launch_bounds__(512) k_logits(
        const float* __restrict__ out_w,
        const float* __restrict__ out_b,
        int hb, float* __restrict__ out,
        const float* __restrict__ embeds,
        float* __restrict__ out_ids, int write_ids, int step) {
    int tid  = threadIdx.x;
    int lane = tid & 31;
    int warp = tid >> 5;                 // 16 warps, 2 rows each
    int r0 = blockIdx.x * LROWS + warp * 2;
    int r1 = r0 + 1;

    const float4* h4 = (const float4*)g_h[hb];
    float4 hv[8];
#pragma unroll
    for (int i = 0; i < 8; i++) hv[i] = h4[lane + 32 * i];

    float t0 = 0.f, t1 = 0.f;
    if (r0 < V) {
        const float4* w0 = (const float4*)(out_w + (size_t)r0 * H);
#pragma unroll
        for (int i = 0; i < 8; i++) t0 += dot4(__ldcs(w0 + lane + 32 * i), hv[i]);
    }
    if (r1 < V) {
        const float4* w1 = (const float4*)(out_w + (size_t)r1 * H);
#pragma unroll
        for (int i = 0; i < 8; i++) t1 += dot4(__ldcs(w1 + lane + 32 * i), hv[i]);
    }
    for (int off = 16; off > 0; off >>= 1) {
        t0 += __shfl_down_sync(0xffffffffu, t0, off);
        t1 += __shfl_down_sync(0xffffffffu, t1, off);
    }

    __shared__ float bv[32];
    __shared__ int   bix[32];
    __shared__ int   s_last;
    if (lane == 0) {
        float l0 = -INFINITY, l1 = -INFINITY;
        if (r0 < V) { l0 = t0 + out_b[r0]; __stcs(out + r0, l0); }
        if (r1 < V) { l1 = t1 + out_b[r1]; __stcs(out + r1, l1); }
        bv[warp * 2] = l0;     bix[warp * 2] = r0;
        bv[warp * 2 + 1] = l1; bix[warp * 2 + 1] = r1;
    }
    __syncthreads();
    if (tid == 0) {
        float best = bv[0]; int bj = bix[0];
#pragma unroll
        for (int w = 1; w < 32; w++)
            if (bv[w] > best) { best = bv[w]; bj = bix[w]; }
        g_pval[blockIdx.x] = best;
        g_pidx[blockIdx.x] = bj;
        __threadfence();
        s_last = (atomicAdd(&g_cnt2, 1u) == gridDim.x - 1);
    }
    __syncthreads();
    if (!s_last) return;
    if (tid == 0) g_cnt2 = 0;

    // -------- final argmax (first-max, matches jnp.argmax) + gather ------
    float best = -INFINITY;
    int bidx = 0x7fffffff;
    int nb = gridDim.x;
    for (int i = tid; i < nb; i += 512) {
        float v = g_pval[i]; int ix = g_pidx[i];
        if (v > best || (v == best && ix < bidx)) { best = v; bidx = ix; }
    }
    __shared__ float sv[512];
    __shared__ int   si[512];
    sv[tid] = best; si[tid] = bidx;
    __syncthreads();
    for (int off = 256; off > 0; off >>= 1) {
        if (tid < off) {
            float v2 = sv[tid + off]; int i2 = si[tid + off];
            if (v2 > sv[tid] || (v2 == sv[tid] && i2 < si[tid])) {
                sv[tid] = v2; si[tid] = i2;
            }
        }
        __syncthreads();
    }
    int idx = si[0];
    for (int k = tid; k < H; k += 512)
        g_prev[k] = embeds[(size_t)idx * H + k];
    if (tid == 0 && write_ids) out_ids[step] = (float)idx;
    __syncthreads();
    if (tid == 0) {
        __threadfence();                       // g_prev visible at L2
        atomicAdd(&g_prev_ready, 1u);          // release the spin kernel
    }
}

// ---------------- launch ---------------------------------------------------
extern "C" void kernel_launch(void* const* d_in, const int* in_sizes, int n_in,
                              void* d_out, int out_size) {
    const void*  seq    = d_in[0];
    const float* embeds = (const float*)d_in[1];
    const float* ew_ih  = (const float*)d_in[2];
    const float* ew_hh  = (const float*)d_in[3];
    const float* eb_ih  = (const float*)d_in[4];
    const float* eb_hh  = (const float*)d_in[5];
    const float* dw_ih  = (const float*)d_in[6];
    const float* dw_hh  = (const float*)d_in[7];
    const float* db_ih  = (const float*)d_in[8];
    const float* db_hh  = (const float*)d_in[9];
    const float* out_w  = (const float*)d_in[10];
    const float* out_b  = (const float*)d_in[11];
    const float* wa     = (const float*)d_in[12];
    float* out = (float*)d_out;

    int write_ids = (out_size >= T * V + T) ? 1 : 0;

    static cudaStream_t s2 = nullptr;
    static cudaEvent_t evFork = nullptr, evJoin = nullptr;
    if (!s2) {
        cudaStreamCreateWithFlags(&s2, cudaStreamNonBlocking);
        cudaEventCreateWithFlags(&evFork, cudaEventDisableTiming);
        cudaEventCreateWithFlags(&evJoin, cudaEventDisableTiming);
    }

    k_init<<<256, 256>>>(seq, out, out_size);

    // hoisted input projection: W_ih read once for all T steps
    k_xproj<<<H / 2, 256>>>(ew_ih, eb_ih, eb_hh, embeds);

    // encoder recurrence (R13 form): only W_hh@h per step
    for (int s = 0; s < T; s++)
        k_lstm_enc<<<H / 2, 256>>>(ew_hh, s, s & 1);

    // step 0 front end (on main)
    k_qattn<<<32, 256>>>(wa, 0);
    k_dec_pre<<<H / 2, 256>>>(dw_ih, dw_hh, 0);
    k_dec_fin<<<H / 2, 256>>>(dw_ih, db_ih, db_hh, 0);

    // fork s2 after the front end; all later deps flow via s2 order + flag
    cudaEventRecord(evFork, 0);
    cudaStreamWaitEvent(s2, evFork, 0);

    for (int d = 0; d < T; d++) {
        int bi = d & 1;
        if (d > 0) cudaStreamWaitEvent(0, evJoin, 0);   // dec stage d done
        k_logits<<<NLB, 512>>>(out_w, out_b, 1 - bi,
                               out + (size_t)d * V,
                               embeds, out + (size_t)T * V,
                               write_ids, d);
        if (d + 1 < T) {
            // s2, concurrent with logits(d): stage d+1 (spin on argmax flag)
            k_qattn<<<32, 256, 0, s2>>>(wa, (d + 1) & 1);
            k_dec_pre<<<H / 2, 256, 0, s2>>>(dw_ih, dw_hh, (d + 1) & 1);
            k_dec_fin_spin<<<H / 2, 256, 0, s2>>>(dw_ih, db_ih, db_hh,
                                                  (d + 1) & 1,
                                                  (unsigned)(d + 1));
            cudaEventRecord(evJoin, s2);
        }
    }
}

// round 16
// speedup vs baseline: 1.2777x; 1.2777x over previous
#include <cuda_runtime.h>
#include <math.h>

#define V 50257
#define H 1024
#define T 10
#define LROWS 32
#define NLB ((V + LROWS - 1) / LROWS)   // 1571 logits blocks (512 threads each)

// ---------------- device scratch (no allocations allowed) ----------------
__device__ __align__(16) float g_h[2][H];
__device__ __align__(16) float g_c[2][H];
__device__ __align__(16) float g_enc[T * H];
__device__ __align__(16) float g_prev[H];
__device__ __align__(16) float g_q[H];
__device__ __align__(16) float g_ctx[H];
__device__ __align__(16) float g_gate[4 * H];    // decoder partial gate sums
__device__ __align__(16) float g_xproj[T * 4 * H]; // enc W_ih@x_t + biases
__device__ int   g_tok[T];
__device__ float g_pval[NLB + 32];
__device__ int   g_pidx[NLB + 32];
__device__ unsigned int g_cnt1;
__device__ unsigned int g_cnt2;

__device__ __forceinline__ float sigm(float x) { return 1.f / (1.f + expf(-x)); }
__device__ __forceinline__ float dot4(float4 a, float4 b) {
    return a.x * b.x + a.y * b.y + a.z * b.z + a.w * b.w;
}

// ---------------- init: tokens, states, poison-safe tail zero -------------
__global__ void k_init(const void* __restrict__ seq_raw,
                       float* __restrict__ out, int out_size) {
    int tid = blockIdx.x * blockDim.x + threadIdx.x;
    if (tid == 0) {
        const long long* s64 = (const long long*)seq_raw;
        bool ok64 = true;
        for (int i = 0; i < T; i++) {
            long long v = s64[i];
            if (v < 0 || v >= V) { ok64 = false; break; }
        }
        const int* s32 = (const int*)seq_raw;
        for (int i = 0; i < T; i++) g_tok[i] = ok64 ? (int)s64[i] : s32[i];
        g_cnt1 = 0; g_cnt2 = 0;
    }
    int stride = gridDim.x * blockDim.x;
    for (int i = tid; i < H; i += stride) {
        g_h[0][i] = 0.f; g_c[0][i] = 0.f; g_prev[i] = 0.f;
    }
    // logits region [0, T*V) is fully overwritten each step; zero only the tail
    for (int i = T * V + tid; i < out_size; i += stride) out[i] = 0.f;
}

// ------- hoisted input projection: xproj[t] = W_ih x_t + b_ih + b_hh ------
__global__ void k_xproj(const float* __restrict__ w_ih,
                        const float* __restrict__ b_ih,
                        const float* __restrict__ b_hh,
                        const float* __restrict__ embeds) {
    int tid  = threadIdx.x;
    int warp = tid >> 5;
    int lane = tid & 31;
    int j    = blockIdx.x * 2 + (warp >> 2);
    int gate = warp & 3;

    const float4* wi = (const float4*)w_ih + (size_t)(gate * H + j) * 256;
    float4 w[8];
#pragma unroll
    for (int i = 0; i < 8; i++) w[i] = wi[lane + 32 * i];

    float acc[T];
#pragma unroll
    for (int t = 0; t < T; t++) {
        const float4* x4 = (const float4*)(embeds + (size_t)g_tok[t] * H);
        float a = 0.f;
#pragma unroll
        for (int i = 0; i < 8; i++) a += dot4(w[i], x4[lane + 32 * i]);
        acc[t] = a;
    }
#pragma unroll
    for (int t = 0; t < T; t++)
        for (int off = 16; off > 0; off >>= 1)
            acc[t] += __shfl_down_sync(0xffffffffu, acc[t], off);
    if (lane == 0) {
        int row = gate * H + j;
        float b = b_ih[row] + b_hh[row];
#pragma unroll
        for (int t = 0; t < T; t++)
            g_xproj[t * 4 * H + row] = acc[t] + b;
    }
}

// ------- encoder LSTM step: hidden part only (W_hh@h), 16MB/step ---------
__global__ void k_lstm_enc(const float* __restrict__ w_hh,
                           int step, int bi) {
    int tid  = threadIdx.x;
    int warp = tid >> 5;
    int lane = tid & 31;
    int j    = blockIdx.x * 2 + (warp >> 2);
    int gate = warp & 3;

    const float4* h4 = (const float4*)g_h[bi];
    const float4* wh = (const float4*)w_hh + (size_t)(gate * H + j) * 256;

    float acc = 0.f;
#pragma unroll
    for (int i = 0; i < 8; i++) {
        int k = lane + 32 * i;
        acc += dot4(wh[k], h4[k]);
    }
    for (int off = 16; off > 0; off >>= 1)
        acc += __shfl_down_sync(0xffffffffu, acc, off);

    __shared__ float s[8];
    if (lane == 0) s[warp] = acc;
    __syncthreads();
    if (tid < 2) {
        int u = blockIdx.x * 2 + tid;
        const float* xp = g_xproj + step * 4 * H;
        float gi = s[tid * 4 + 0] + xp[u];
        float gf = s[tid * 4 + 1] + xp[H + u];
        float gg = s[tid * 4 + 2] + xp[2 * H + u];
        float go = s[tid * 4 + 3] + xp[3 * H + u];
        float i_ = sigm(gi), f_ = sigm(gf), g_ = tanhf(gg), o_ = sigm(go);
        float cn = f_ * g_c[bi][u] + i_ * g_;
        float hn = o_ * tanhf(cn);
        g_c[1 - bi][u] = cn;
        g_h[1 - bi][u] = hn;
        g_enc[step * H + u] = hn;
    }
}

// ---------------- q = wa^T h, then last block does softmax+ctx -----------
__global__ void k_qattn(const float* __restrict__ wa, int bi) {
    int tid  = threadIdx.x;
    int lane = tid & 31;
    int warp = tid >> 5;
    int col  = blockIdx.x * 32 + lane;
    const float* h = g_h[bi];

    float acc = 0.f;
    for (int i = warp; i < H; i += 8) acc += h[i] * wa[(size_t)i * H + col];
    __shared__ float s[256];
    s[tid] = acc;
    __syncthreads();
    for (int off = 128; off >= 32; off >>= 1) {
        if (tid < off) s[tid] += s[tid + off];
        __syncthreads();
    }
    if (tid < 32) g_q[col] = s[tid];

    __shared__ int s_last;
    __threadfence();
    if (tid == 0) s_last = (atomicAdd(&g_cnt1, 1u) == gridDim.x - 1);
    __syncthreads();
    if (!s_last) return;
    if (tid == 0) g_cnt1 = 0;

    float at[T];
#pragma unroll
    for (int t = 0; t < T; t++) at[t] = 0.f;
    for (int k = tid; k < H; k += 256) {
        float qv = g_q[k];
#pragma unroll
        for (int t = 0; t < T; t++) at[t] += qv * g_enc[t * H + k];
    }
#pragma unroll
    for (int t = 0; t < T; t++)
        for (int off = 16; off > 0; off >>= 1)
            at[t] += __shfl_down_sync(0xffffffffu, at[t], off);
    __shared__ float s2[T * 8];
    if (lane == 0) {
#pragma unroll
        for (int t = 0; t < T; t++) s2[t * 8 + warp] = at[t];
    }
    __syncthreads();
    __shared__ float sa[T];
    if (tid == 0) {
        float sc[T];
        float m = -INFINITY;
#pragma unroll
        for (int t = 0; t < T; t++) {
            float v = 0.f;
#pragma unroll
            for (int w = 0; w < 8; w++) v += s2[t * 8 + w];
            sc[t] = v;
            m = fmaxf(m, v);
        }
        float sum = 0.f;
#pragma unroll
        for (int t = 0; t < T; t++) { float e = expf(sc[t] - m); sa[t] = e; sum += e; }
#pragma unroll
        for (int t = 0; t < T; t++) sa[t] /= sum;
    }
    __syncthreads();
    for (int k = tid; k < H; k += 256) {
        float v = 0.f;
#pragma unroll
        for (int t = 0; t < T; t++) v += sa[t] * g_enc[t * H + k];
        g_ctx[k] = v;
    }
}

// ------- decoder part 1 (prev-independent): g_gate = Wih[:,H:]ctx + Whh h -
__global__ void k_dec_pre(const float* __restrict__ w_ih,  // (4H, 2H)
                          const float* __restrict__ w_hh,  // (4H, H)
                          int bi) {
    int tid  = threadIdx.x;
    int warp = tid >> 5;
    int lane = tid & 31;
    int j    = blockIdx.x * 2 + (warp >> 2);
    int gate = warp & 3;

    const float4* h4 = (const float4*)g_h[bi];
    const float4* c4 = (const float4*)g_ctx;
    const float4* wi = (const float4*)w_ih + (size_t)(gate * H + j) * 512 + 256;
    const float4* wh = (const float4*)w_hh + (size_t)(gate * H + j) * 256;

    float acc = 0.f;
#pragma unroll
    for (int i = 0; i < 8; i++) {
        int k = lane + 32 * i;
        acc += dot4(wi[k], c4[k]);
        acc += dot4(wh[k], h4[k]);
    }
    for (int off = 16; off > 0; off >>= 1)
        acc += __shfl_down_sync(0xffffffffu, acc, off);
    if (lane == 0) g_gate[gate * H + j] = acc;
}

// ------- decoder part 2 (prev term + cell update) -------------------------
__global__ void k_dec_fin(const float* __restrict__ w_ih,  // (4H, 2H)
                          const float* __restrict__ b_ih,
                          const float* __restrict__ b_hh,
                          int bi) {
    int tid  = threadIdx.x;
    int warp = tid >> 5;
    int lane = tid & 31;
    int j    = blockIdx.x * 2 + (warp >> 2);
    int gate = warp & 3;

    const float4* p4 = (const float4*)g_prev;
    const float4* wi = (const float4*)w_ih + (size_t)(gate * H + j) * 512;

    float acc = 0.f;
#pragma unroll
    for (int i = 0; i < 8; i++) {
        int k = lane + 32 * i;
        float4 v = p4[k];
        v.x = fmaxf(v.x, 0.f); v.y = fmaxf(v.y, 0.f);
        v.z = fmaxf(v.z, 0.f); v.w = fmaxf(v.w, 0.f);
        acc += dot4(wi[k], v);
    }
    for (int off = 16; off > 0; off >>= 1)
        acc += __shfl_down_sync(0xffffffffu, acc, off);

    __shared__ float s[8];
    if (lane == 0) s[warp] = acc;
    __syncthreads();
    if (tid < 2) {
        int u = blockIdx.x * 2 + tid;
        float gi = s[tid * 4 + 0] + g_gate[0 * H + u] + b_ih[u]         + b_hh[u];
        float gf = s[tid * 4 + 1] + g_gate[1 * H + u] + b_ih[H + u]     + b_hh[H + u];
        float gg = s[tid * 4 + 2] + g_gate[2 * H + u] + b_ih[2 * H + u] + b_hh[2 * H + u];
        float go = s[tid * 4 + 3] + g_gate[3 * H + u] + b_ih[3 * H + u] + b_hh[3 * H + u];
        float i_ = sigm(gi), f_ = sigm(gf), g_ = tanhf(gg), o_ = sigm(go);
        float cn = f_ * g_c[bi][u] + i_ * g_;
        float hn = o_ * tanhf(cn);
        g_c[1 - bi][u] = cn;
        g_h[1 - bi][u] = hn;
    }
}

// ---- logits: 512 threads, 16 warps x 2 rows (proven pattern), fused argmax
__global__ void __launch_bounds__(512) k_logits(
        const float* __restrict__ out_w,
        const float* __restrict__ out_b,
        int hb, float* __restrict__ out,
        const float* __restrict__ embeds,
        float* __restrict__ out_ids, int write_ids, int step) {
    int tid  = threadIdx.x;
    int lane = tid & 31;
    int warp = tid >> 5;                 // 16 warps, 2 rows each
    int r0 = blockIdx.x * LROWS + warp * 2;
    int r1 = r0 + 1;

    const float4* h4 = (const float4*)g_h[hb];
    float4 hv[8];
#pragma unroll
    for (int i = 0; i < 8; i++) hv[i] = h4[lane + 32 * i];

    float t0 = 0.f, t1 = 0.f;
    if (r0 < V) {
        const float4* w0 = (const float4*)(out_w + (size_t)r0 * H);
#pragma unroll
        for (int i = 0; i < 8; i++) t0 += dot4(__ldcs(w0 + lane + 32 * i), hv[i]);
    }
    if (r1 < V) {
        const float4* w1 = (const float4*)(out_w + (size_t)r1 * H);
#pragma unroll
        for (int i = 0; i < 8; i++) t1 += dot4(__ldcs(w1 + lane + 32 * i), hv[i]);
    }
    for (int off = 16; off > 0; off >>= 1) {
        t0 += __shfl_down_sync(0xffffffffu, t0, off);
        t1 += __shfl_down_sync(0xffffffffu, t1, off);
    }

    __shared__ float bv[32];
    __shared__ int   bix[32];
    __shared__ int   s_last;
    if (lane == 0) {
        float l0 = -INFINITY, l1 = -INFINITY;
        if (r0 < V) { l0 = t0 + out_b[r0]; __stcs(out + r0, l0); }
        if (r1 < V) { l1 = t1 + out_b[r1]; __stcs(out + r1, l1); }
        bv[warp * 2] = l0;     bix[warp * 2] = r0;
        bv[warp * 2 + 1] = l1; bix[warp * 2 + 1] = r1;
    }
    __syncthreads();
    if (tid == 0) {
        float best = bv[0]; int bj = bix[0];
#pragma unroll
        for (int w = 1; w < 32; w++)
            if (bv[w] > best) { best = bv[w]; bj = bix[w]; }
        g_pval[blockIdx.x] = best;
        g_pidx[blockIdx.x] = bj;
        __threadfence();
        s_last = (atomicAdd(&g_cnt2, 1u) == gridDim.x - 1);
    }
    __syncthreads();
    if (!s_last) return;
    if (tid == 0) g_cnt2 = 0;

    // -------- final argmax (first-max, matches jnp.argmax) + gather ------
    float best = -INFINITY;
    int bidx = 0x7fffffff;
    int nb = gridDim.x;
    for (int i = tid; i < nb; i += 512) {
        float v = g_pval[i]; int ix = g_pidx[i];
        if (v > best || (v == best && ix < bidx)) { best = v; bidx = ix; }
    }
    __shared__ float sv[512];
    __shared__ int   si[512];
    sv[tid] = best; si[tid] = bidx;
    __syncthreads();
    for (int off = 256; off > 0; off >>= 1) {
        if (tid < off) {
            float v2 = sv[tid + off]; int i2 = si[tid + off];
            if (v2 > sv[tid] || (v2 == sv[tid] && i2 < si[tid])) {
                sv[tid] = v2; si[tid] = i2;
            }
        }
        __syncthreads();
    }
    int idx = si[0];
    for (int k = tid; k < H; k += 512)
        g_prev[k] = embeds[(size_t)idx * H + k];
    if (tid == 0 && write_ids) out_ids[step] = (float)idx;
}

// ---------------- launch ---------------------------------------------------
extern "C" void kernel_launch(void* const* d_in, const int* in_sizes, int n_in,
                              void* d_out, int out_size) {
    const void*  seq    = d_in[0];
    const float* embeds = (const float*)d_in[1];
    const float* ew_ih  = (const float*)d_in[2];
    const float* ew_hh  = (const float*)d_in[3];
    const float* eb_ih  = (const float*)d_in[4];
    const float* eb_hh  = (const float*)d_in[5];
    const float* dw_ih  = (const float*)d_in[6];
    const float* dw_hh  = (const float*)d_in[7];
    const float* db_ih  = (const float*)d_in[8];
    const float* db_hh  = (const float*)d_in[9];
    const float* out_w  = (const float*)d_in[10];
    const float* out_b  = (const float*)d_in[11];
    const float* wa     = (const float*)d_in[12];
    float* out = (float*)d_out;

    int write_ids = (out_size >= T * V + T) ? 1 : 0;

    static cudaStream_t s2 = nullptr;
    static cudaEvent_t evFork = nullptr, evJoin = nullptr;
    if (!s2) {
        int loPri, hiPri;
        cudaDeviceGetStreamPriorityRange(&loPri, &hiPri);
        cudaStreamCreateWithPriority(&s2, cudaStreamNonBlocking, hiPri);
        cudaEventCreateWithFlags(&evFork, cudaEventDisableTiming);
        cudaEventCreateWithFlags(&evJoin, cudaEventDisableTiming);
    }

    k_init<<<16, 256>>>(seq, out, out_size);

    // hoisted input projection: W_ih read once for all T steps
    k_xproj<<<H / 2, 256>>>(ew_ih, eb_ih, eb_hh, embeds);

    // encoder recurrence: only W_hh@h per step (16MB)
    for (int s = 0; s < T; s++)
        k_lstm_enc<<<H / 2, 256>>>(ew_hh, s, s & 1);

    // step 0 front end
    k_qattn<<<32, 256>>>(wa, 0);
    k_dec_pre<<<H / 2, 256>>>(dw_ih, dw_hh, 0);
    k_dec_fin<<<H / 2, 256>>>(dw_ih, db_ih, db_hh, 0);

    for (int d = 0; d < T; d++) {
        int bi = d & 1;
        // overlap with logits(d): qattn(d+1) + dec_pre(d+1) on side stream
        if (d + 1 < T) {
            cudaEventRecord(evFork, 0);          // after dec_fin(d)
            cudaStreamWaitEvent(s2, evFork, 0);
            k_qattn<<<32, 256, 0, s2>>>(wa, (d + 1) & 1);
            k_dec_pre<<<H / 2, 256, 0, s2>>>(dw_ih, dw_hh, (d + 1) & 1);
            cudaEventRecord(evJoin, s2);
        }
        k_logits<<<NLB, 512>>>(out_w, out_b, 1 - bi,
                               out + (size_t)d * V,
                               embeds, out + (size_t)T * V,
                               write_ids, d);
        if (d + 1 < T) {
            cudaStreamWaitEvent(0, evJoin, 0);
            k_dec_fin<<<H / 2, 256>>>(dw_ih, db_ih, db_hh, (d + 1) & 1);
        }
    }
}

// round 17
// speedup vs baseline: 1.2996x; 1.0172x over previous
#include <cuda_runtime.h>
#include <math.h>

#define V 50257
#define H 1024
#define T 10
#define LROWS 32
#define NLB ((V + LROWS - 1) / LROWS)   // 1571 logits blocks (512 threads each)

// ---------------- device scratch (no allocations allowed) ----------------
__device__ __align__(16) float g_h[2][H];
__device__ __align__(16) float g_c[2][H];
__device__ __align__(16) float g_enc[T * H];
__device__ __align__(16) float g_prev[H];
__device__ __align__(16) float g_q[H];
__device__ __align__(16) float g_ctx[H];
__device__ __align__(16) float g_gate[4 * H];    // decoder partial gate sums
__device__ __align__(16) float g_xproj[T * 4 * H]; // enc W_ih@x_t + biases
__device__ int   g_tok[T];
__device__ unsigned long long g_amax;            // packed (ordered_val, ~idx)
__device__ unsigned int g_cnt1;
__device__ unsigned int g_cnt2;

__device__ __forceinline__ float sigm(float x) { return 1.f / (1.f + expf(-x)); }
__device__ __forceinline__ float dot4(float4 a, float4 b) {
    return a.x * b.x + a.y * b.y + a.z * b.z + a.w * b.w;
}
// monotonic float->u32 mapping (total order preserved)
__device__ __forceinline__ unsigned int f2ord(float f) {
    unsigned int b = __float_as_uint(f);
    return (b & 0x80000000u) ? ~b : (b | 0x80000000u);
}

// ---------------- init: tokens, states, poison-safe tail zero -------------
__global__ void k_init(const void* __restrict__ seq_raw,
                       float* __restrict__ out, int out_size) {
    int tid = blockIdx.x * blockDim.x + threadIdx.x;
    if (tid == 0) {
        const long long* s64 = (const long long*)seq_raw;
        bool ok64 = true;
        for (int i = 0; i < T; i++) {
            long long v = s64[i];
            if (v < 0 || v >= V) { ok64 = false; break; }
        }
        const int* s32 = (const int*)seq_raw;
        for (int i = 0; i < T; i++) g_tok[i] = ok64 ? (int)s64[i] : s32[i];
        g_cnt1 = 0; g_cnt2 = 0; g_amax = 0ull;
    }
    int stride = gridDim.x * blockDim.x;
    for (int i = tid; i < H; i += stride) {
        g_h[0][i] = 0.f; g_c[0][i] = 0.f; g_prev[i] = 0.f;
    }
    // logits region [0, T*V) is fully overwritten each step; zero only the tail
    for (int i = T * V + tid; i < out_size; i += stride) out[i] = 0.f;
}

// ------- hoisted input projection: xproj[t] = W_ih x_t + b_ih + b_hh ------
__global__ void k_xproj(const float* __restrict__ w_ih,
                        const float* __restrict__ b_ih,
                        const float* __restrict__ b_hh,
                        const float* __restrict__ embeds) {
    int tid  = threadIdx.x;
    int warp = tid >> 5;
    int lane = tid & 31;
    int j    = blockIdx.x * 2 + (warp >> 2);
    int gate = warp & 3;

    const float4* wi = (const float4*)w_ih + (size_t)(gate * H + j) * 256;
    float4 w[8];
#pragma unroll
    for (int i = 0; i < 8; i++) w[i] = wi[lane + 32 * i];

    float acc[T];
#pragma unroll
    for (int t = 0; t < T; t++) {
        const float4* x4 = (const float4*)(embeds + (size_t)g_tok[t] * H);
        float a = 0.f;
#pragma unroll
        for (int i = 0; i < 8; i++) a += dot4(w[i], x4[lane + 32 * i]);
        acc[t] = a;
    }
#pragma unroll
    for (int t = 0; t < T; t++)
        for (int off = 16; off > 0; off >>= 1)
            acc[t] += __shfl_down_sync(0xffffffffu, acc[t], off);
    if (lane == 0) {
        int row = gate * H + j;
        float b = b_ih[row] + b_hh[row];
#pragma unroll
        for (int t = 0; t < T; t++)
            g_xproj[t * 4 * H + row] = acc[t] + b;
    }
}

// ------- encoder LSTM step: hidden part only (W_hh@h), 16MB/step ---------
__global__ void k_lstm_enc(const float* __restrict__ w_hh,
                           int step, int bi) {
    int tid  = threadIdx.x;
    int warp = tid >> 5;
    int lane = tid & 31;
    int j    = blockIdx.x * 2 + (warp >> 2);
    int gate = warp & 3;

    const float4* h4 = (const float4*)g_h[bi];
    const float4* wh = (const float4*)w_hh + (size_t)(gate * H + j) * 256;

    float acc = 0.f;
#pragma unroll
    for (int i = 0; i < 8; i++) {
        int k = lane + 32 * i;
        acc += dot4(wh[k], h4[k]);
    }
    for (int off = 16; off > 0; off >>= 1)
        acc += __shfl_down_sync(0xffffffffu, acc, off);

    __shared__ float s[8];
    if (lane == 0) s[warp] = acc;
    __syncthreads();
    if (tid < 2) {
        int u = blockIdx.x * 2 + tid;
        const float* xp = g_xproj + step * 4 * H;
        float gi = s[tid * 4 + 0] + xp[u];
        float gf = s[tid * 4 + 1] + xp[H + u];
        float gg = s[tid * 4 + 2] + xp[2 * H + u];
        float go = s[tid * 4 + 3] + xp[3 * H + u];
        float i_ = sigm(gi), f_ = sigm(gf), g_ = tanhf(gg), o_ = sigm(go);
        float cn = f_ * g_c[bi][u] + i_ * g_;
        float hn = o_ * tanhf(cn);
        g_c[1 - bi][u] = cn;
        g_h[1 - bi][u] = hn;
        g_enc[step * H + u] = hn;
    }
}

// ---------------- q = wa^T h, then last block does softmax+ctx -----------
__global__ void k_qattn(const float* __restrict__ wa, int bi) {
    int tid  = threadIdx.x;
    int lane = tid & 31;
    int warp = tid >> 5;
    int col  = blockIdx.x * 32 + lane;
    const float* h = g_h[bi];

    float acc = 0.f;
    for (int i = warp; i < H; i += 8) acc += h[i] * wa[(size_t)i * H + col];
    __shared__ float s[256];
    s[tid] = acc;
    __syncthreads();
    for (int off = 128; off >= 32; off >>= 1) {
        if (tid < off) s[tid] += s[tid + off];
        __syncthreads();
    }
    if (tid < 32) g_q[col] = s[tid];

    __shared__ int s_last;
    __threadfence();
    if (tid == 0) s_last = (atomicAdd(&g_cnt1, 1u) == gridDim.x - 1);
    __syncthreads();
    if (!s_last) return;
    if (tid == 0) g_cnt1 = 0;

    float at[T];
#pragma unroll
    for (int t = 0; t < T; t++) at[t] = 0.f;
    for (int k = tid; k < H; k += 256) {
        float qv = g_q[k];
#pragma unroll
        for (int t = 0; t < T; t++) at[t] += qv * g_enc[t * H + k];
    }
#pragma unroll
    for (int t = 0; t < T; t++)
        for (int off = 16; off > 0; off >>= 1)
            at[t] += __shfl_down_sync(0xffffffffu, at[t], off);
    __shared__ float s2[T * 8];
    if (lane == 0) {
#pragma unroll
        for (int t = 0; t < T; t++) s2[t * 8 + warp] = at[t];
    }
    __syncthreads();
    __shared__ float sa[T];
    if (tid == 0) {
        float sc[T];
        float m = -INFINITY;
#pragma unroll
        for (int t = 0; t < T; t++) {
            float v = 0.f;
#pragma unroll
            for (int w = 0; w < 8; w++) v += s2[t * 8 + w];
            sc[t] = v;
            m = fmaxf(m, v);
        }
        float sum = 0.f;
#pragma unroll
        for (int t = 0; t < T; t++) { float e = expf(sc[t] - m); sa[t] = e; sum += e; }
#pragma unroll
        for (int t = 0; t < T; t++) sa[t] /= sum;
    }
    __syncthreads();
    for (int k = tid; k < H; k += 256) {
        float v = 0.f;
#pragma unroll
        for (int t = 0; t < T; t++) v += sa[t] * g_enc[t * H + k];
        g_ctx[k] = v;
    }
}

// ------- decoder part 1 (prev-independent): g_gate = Wih[:,H:]ctx + Whh h -
__global__ void k_dec_pre(const float* __restrict__ w_ih,  // (4H, 2H)
                          const float* __restrict__ w_hh,  // (4H, H)
                          int bi) {
    int tid  = threadIdx.x;
    int warp = tid >> 5;
    int lane = tid & 31;
    int j    = blockIdx.x * 2 + (warp >> 2);
    int gate = warp & 3;

    const float4* h4 = (const float4*)g_h[bi];
    const float4* c4 = (const float4*)g_ctx;
    const float4* wi = (const float4*)w_ih + (size_t)(gate * H + j) * 512 + 256;
    const float4* wh = (const float4*)w_hh + (size_t)(gate * H + j) * 256;

    float acc = 0.f;
#pragma unroll
    for (int i = 0; i < 8; i++) {
        int k = lane + 32 * i;
        acc += dot4(wi[k], c4[k]);
        acc += dot4(wh[k], h4[k]);
    }
    for (int off = 16; off > 0; off >>= 1)
        acc += __shfl_down_sync(0xffffffffu, acc, off);
    if (lane == 0) g_gate[gate * H + j] = acc;
}

// ------- decoder part 2 (prev term + cell update) -------------------------
__global__ void k_dec_fin(const float* __restrict__ w_ih,  // (4H, 2H)
                          const float* __restrict__ b_ih,
                          const float* __restrict__ b_hh,
                          int bi) {
    int tid  = threadIdx.x;
    int warp = tid >> 5;
    int lane = tid & 31;
    int j    = blockIdx.x * 2 + (warp >> 2);
    int gate = warp & 3;

    const float4* p4 = (const float4*)g_prev;
    const float4* wi = (const float4*)w_ih + (size_t)(gate * H + j) * 512;

    float acc = 0.f;
#pragma unroll
    for (int i = 0; i < 8; i++) {
        int k = lane + 32 * i;
        float4 v = p4[k];
        v.x = fmaxf(v.x, 0.f); v.y = fmaxf(v.y, 0.f);
        v.z = fmaxf(v.z, 0.f); v.w = fmaxf(v.w, 0.f);
        acc += dot4(wi[k], v);
    }
    for (int off = 16; off > 0; off >>= 1)
        acc += __shfl_down_sync(0xffffffffu, acc, off);

    __shared__ float s[8];
    if (lane == 0) s[warp] = acc;
    __syncthreads();
    if (tid < 2) {
        int u = blockIdx.x * 2 + tid;
        float gi = s[tid * 4 + 0] + g_gate[0 * H + u] + b_ih[u]         + b_hh[u];
        float gf = s[tid * 4 + 1] + g_gate[1 * H + u] + b_ih[H + u]     + b_hh[H + u];
        float gg = s[tid * 4 + 2] + g_gate[2 * H + u] + b_ih[2 * H + u] + b_hh[2 * H + u];
        float go = s[tid * 4 + 3] + g_gate[3 * H + u] + b_ih[3 * H + u] + b_hh[3 * H + u];
        float i_ = sigm(gi), f_ = sigm(gf), g_ = tanhf(gg), o_ = sigm(go);
        float cn = f_ * g_c[bi][u] + i_ * g_;
        float hn = o_ * tanhf(cn);
        g_c[1 - bi][u] = cn;
        g_h[1 - bi][u] = hn;
    }
}

// ---- logits: 512 threads, 16 warps x 2 rows; argmax via packed atomicMax -
__global__ void __launch_bounds__(512) k_logits(
        const float* __restrict__ out_w,
        const float* __restrict__ out_b,
        int hb, float* __restrict__ out,
        const float* __restrict__ embeds,
        float* __restrict__ out_ids, int write_ids, int step) {
    int tid  = threadIdx.x;
    int lane = tid & 31;
    int warp = tid >> 5;                 // 16 warps, 2 rows each
    int r0 = blockIdx.x * LROWS + warp * 2;
    int r1 = r0 + 1;

    const float4* h4 = (const float4*)g_h[hb];
    float4 hv[8];
#pragma unroll
    for (int i = 0; i < 8; i++) hv[i] = h4[lane + 32 * i];

    float t0 = 0.f, t1 = 0.f;
    if (r0 < V) {
        const float4* w0 = (const float4*)(out_w + (size_t)r0 * H);
#pragma unroll
        for (int i = 0; i < 8; i++) t0 += dot4(__ldcs(w0 + lane + 32 * i), hv[i]);
    }
    if (r1 < V) {
        const float4* w1 = (const float4*)(out_w + (size_t)r1 * H);
#pragma unroll
        for (int i = 0; i < 8; i++) t1 += dot4(__ldcs(w1 + lane + 32 * i), hv[i]);
    }
    for (int off = 16; off > 0; off >>= 1) {
        t0 += __shfl_down_sync(0xffffffffu, t0, off);
        t1 += __shfl_down_sync(0xffffffffu, t1, off);
    }

    __shared__ unsigned long long bk[16];
    __shared__ int s_last;
    if (lane == 0) {
        unsigned long long k0 = 0ull, k1 = 0ull;
        if (r0 < V) {
            float l0 = t0 + out_b[r0];
            __stcs(out + r0, l0);
            k0 = ((unsigned long long)f2ord(l0) << 32) | (0xFFFFFFFFu - (unsigned)r0);
        }
        if (r1 < V) {
            float l1 = t1 + out_b[r1];
            __stcs(out + r1, l1);
            k1 = ((unsigned long long)f2ord(l1) << 32) | (0xFFFFFFFFu - (unsigned)r1);
        }
        bk[warp] = (k0 > k1) ? k0 : k1;
    }
    __syncthreads();
    if (tid == 0) {
        unsigned long long best = bk[0];
#pragma unroll
        for (int w = 1; w < 16; w++) if (bk[w] > best) best = bk[w];
        atomicMax(&g_amax, best);
        __threadfence();
        s_last = (atomicAdd(&g_cnt2, 1u) == gridDim.x - 1);
    }
    __syncthreads();
    if (!s_last) return;

    // -------- last block: decode packed argmax, gather embedding ---------
    __shared__ int s_idx;
    if (tid == 0) {
        unsigned long long packed = atomicAdd(&g_amax, 0ull);
        s_idx = (int)(0xFFFFFFFFu - (unsigned)(packed & 0xFFFFFFFFu));
        g_amax = 0ull;          // reset for next step (kernel-ordered)
        g_cnt2 = 0;
    }
    __syncthreads();
    int idx = s_idx;
    for (int k = tid; k < H; k += 512)
        g_prev[k] = embeds[(size_t)idx * H + k];
    if (tid == 0 && write_ids) out_ids[step] = (float)idx;
}

// ---------------- launch ---------------------------------------------------
extern "C" void kernel_launch(void* const* d_in, const int* in_sizes, int n_in,
                              void* d_out, int out_size) {
    const void*  seq    = d_in[0];
    const float* embeds = (const float*)d_in[1];
    const float* ew_ih  = (const float*)d_in[2];
    const float* ew_hh  = (const float*)d_in[3];
    const float* eb_ih  = (const float*)d_in[4];
    const float* eb_hh  = (const float*)d_in[5];
    const float* dw_ih  = (const float*)d_in[6];
    const float* dw_hh  = (const float*)d_in[7];
    const float* db_ih  = (const float*)d_in[8];
    const float* db_hh  = (const float*)d_in[9];
    const float* out_w  = (const float*)d_in[10];
    const float* out_b  = (const float*)d_in[11];
    const float* wa     = (const float*)d_in[12];
    float* out = (float*)d_out;

    int write_ids = (out_size >= T * V + T) ? 1 : 0;

    static cudaStream_t s2 = nullptr;
    static cudaEvent_t evFork = nullptr, evJoin = nullptr;
    if (!s2) {
        int loPri, hiPri;
        cudaDeviceGetStreamPriorityRange(&loPri, &hiPri);
        cudaStreamCreateWithPriority(&s2, cudaStreamNonBlocking, hiPri);
        cudaEventCreateWithFlags(&evFork, cudaEventDisableTiming);
        cudaEventCreateWithFlags(&evJoin, cudaEventDisableTiming);
    }

    k_init<<<16, 256>>>(seq, out, out_size);

    // hoisted input projection: W_ih read once for all T steps
    k_xproj<<<H / 2, 256>>>(ew_ih, eb_ih, eb_hh, embeds);

    // encoder recurrence: only W_hh@h per step (16MB)
    for (int s = 0; s < T; s++)
        k_lstm_enc<<<H / 2, 256>>>(ew_hh, s, s & 1);

    // step 0 front end
    k_qattn<<<32, 256>>>(wa, 0);
    k_dec_pre<<<H / 2, 256>>>(dw_ih, dw_hh, 0);
    k_dec_fin<<<H / 2, 256>>>(dw_ih, db_ih, db_hh, 0);

    for (int d = 0; d < T; d++) {
        int bi = d & 1;
        // overlap with logits(d): qattn(d+1) + dec_pre(d+1) on side stream
        if (d + 1 < T) {
            cudaEventRecord(evFork, 0);          // after dec_fin(d)
            cudaStreamWaitEvent(s2, evFork, 0);
            k_qattn<<<32, 256, 0, s2>>>(wa, (d + 1) & 1);
            k_dec_pre<<<H / 2, 256, 0, s2>>>(dw_ih, dw_hh, (d + 1) & 1);
            cudaEventRecord(evJoin, s2);
        }
        k_logits<<<NLB, 512>>>(out_w, out_b, 1 - bi,
                               out + (size_t)d * V,
                               embeds, out + (size_t)T * V,
                               write_ids, d);
        if (d + 1 < T) {
            cudaStreamWaitEvent(0, evJoin, 0);
            k_dec_fin<<<H / 2, 256>>>(dw_ih, db_ih, db_hh, (d + 1) & 1);
        }
    }
}